// round 9
// baseline (speedup 1.0000x reference)
#include <cuda_runtime.h>
#include <cuda_bf16.h>
#include <cstdint>
#include <math.h>

#define BN    8
#define CINC  256
#define CMID  128
#define COUTC 256
#define HH    128
#define WW    128
#define HWSZ  16384

typedef uint32_t u32;

// ---------------- scratch (static __device__ — allocation-free) ----------------
__device__ float g_y[4][BN * CMID * HH * WW];  // branch conv outputs (post-relu)
__device__ float g_S[BN * CMID * HH * WW];     // scan scratch (fp32)
// pre-split activations, channel-pair packed bf16x2: [b][cpair][h][w]
__device__ u32 g_xh[BN * 128 * HH * WW];
__device__ u32 g_xl[BN * 128 * HH * WW];
__device__ u32 g_Sh[BN * 64 * HH * WW];
__device__ u32 g_Sl[BN * 64 * HH * WW];
// bf16-split weights: branch [tap=br*9+kh*3+kw][co=128][cipair]
__device__ __align__(16) __nv_bfloat162 g_wAh[36 * 128 * 128];
__device__ __align__(16) __nv_bfloat162 g_wAl[36 * 128 * 128];
__device__ __align__(16) __nv_bfloat162 g_w2h[9 * 256 * 64];   // [t][co=256][cipair=64]
__device__ __align__(16) __nv_bfloat162 g_w2l[9 * 256 * 64];
__device__ __align__(16) __nv_bfloat162 g_w1h[256 * 128];      // [co=256][cipair=128]
__device__ __align__(16) __nv_bfloat162 g_w1l[256 * 128];

// ---------------- helpers ----------------
__device__ __forceinline__ u32 smem_u32(const void* p) {
    u32 a;
    asm("{ .reg .u64 t; cvta.to.shared.u64 t, %1; cvt.u32.u64 %0, t; }" : "=r"(a) : "l"(p));
    return a;
}

// XOR swizzle: byte bits [6:4] ^= bits [9:7]  (rows are 128B)
#define SWZ(off) ((off) ^ (((off) >> 3) & 0x70))

__device__ __forceinline__ void ldm_x4(u32* r, u32 addr) {
    asm volatile("ldmatrix.sync.aligned.m8n8.x4.shared.b16 {%0,%1,%2,%3}, [%4];"
                 : "=r"(r[0]), "=r"(r[1]), "=r"(r[2]), "=r"(r[3]) : "r"(addr));
}
__device__ __forceinline__ void mma16816(float* d, const u32* a, const u32* b) {
    asm volatile("mma.sync.aligned.m16n8k16.row.col.f32.bf16.bf16.f32 "
                 "{%0,%1,%2,%3}, {%4,%5,%6,%7}, {%8,%9}, {%0,%1,%2,%3};"
                 : "+f"(d[0]), "+f"(d[1]), "+f"(d[2]), "+f"(d[3])
                 : "r"(a[0]), "r"(a[1]), "r"(a[2]), "r"(a[3]), "r"(b[0]), "r"(b[1]));
}
__device__ __forceinline__ void cpa16(u32 d, const void* s) {
    asm volatile("cp.async.cg.shared.global [%0], [%1], 16;" :: "r"(d), "l"(s));
}
#define CPA_COMMIT() asm volatile("cp.async.commit_group;" ::: "memory")
#define CPA_WAIT0()  asm volatile("cp.async.wait_group 0;" ::: "memory")

// smem layout: two A buffers (hi+lo 16KB each), two extended B buffers (132 rows, hi+lo)
#define BSZ    16896                    // 132 * 128 bytes
#define OFF_A0 0
#define OFF_A1 32768
#define OFF_B0 65536
#define OFF_B1 (65536 + 2 * BSZ)        // 99328
#define SMEM_BYTES (OFF_B1 + 2 * BSZ)   // 133120

__device__ __forceinline__ u32 packsplit(float v0, float v1, u32& lo) {
    __nv_bfloat16 h0 = __float2bfloat16(v0), h1 = __float2bfloat16(v1);
    __nv_bfloat16 l0 = __float2bfloat16(v0 - __bfloat162float(h0));
    __nv_bfloat16 l1 = __float2bfloat16(v1 - __bfloat162float(h1));
    u32 hv;
    asm("mov.b32 %0, {%1, %2};" : "=r"(hv) : "h"(*(unsigned short*)&h0), "h"(*(unsigned short*)&h1));
    asm("mov.b32 %0, {%1, %2};" : "=r"(lo) : "h"(*(unsigned short*)&l0), "h"(*(unsigned short*)&l1));
    return hv;
}

// ---------------- weight repack (+BN scale fold, bf16 hi/lo split) ----------------
__global__ void k_repack_br(const float* __restrict__ w, const float* __restrict__ s, int br)
{
    int slot = blockIdx.x * 256 + threadIdx.x;       // 9*128*128
    if (slot >= 147456) return;
    int pair = slot & 127;
    int co   = (slot >> 7) & 127;
    int t    = slot >> 14;
    int kh = t / 3, kw = t % 3;
    int ci = pair * 2;
    float sc = s[co];
    float v0 = w[((co * CINC + ci)     * 3 + kh) * 3 + kw] * sc;
    float v1 = w[((co * CINC + ci + 1) * 3 + kh) * 3 + kw] * sc;
    u32 lo, hi = packsplit(v0, v1, lo);
    int idx = ((br * 9 + t) * 128 + co) * 128 + pair;
    *(u32*)&g_wAh[idx] = hi;
    *(u32*)&g_wAl[idx] = lo;
}

__global__ void k_repack_w2(const float* __restrict__ w, const float* __restrict__ s)
{
    int slot = blockIdx.x * 256 + threadIdx.x;       // 9*256*64
    if (slot >= 147456) return;
    int pair = slot & 63;
    int co   = (slot >> 6) & 255;
    int t    = slot >> 14;
    int kh = t / 3, kw = t % 3;
    int ci = pair * 2;
    float sc = s[co];
    float v0 = w[((co * CMID + ci)     * 3 + kh) * 3 + kw] * sc;
    float v1 = w[((co * CMID + ci + 1) * 3 + kh) * 3 + kw] * sc;
    u32 lo, hi = packsplit(v0, v1, lo);
    int idx = (t * 256 + co) * 64 + pair;
    *(u32*)&g_w2h[idx] = hi;
    *(u32*)&g_w2l[idx] = lo;
}

__global__ void k_repack_w1(const float* __restrict__ w, const float* __restrict__ s)
{
    int slot = blockIdx.x * 256 + threadIdx.x;       // 256*128
    if (slot >= 32768) return;
    int pair = slot & 127;
    int co   = slot >> 7;
    int ci = pair * 2;
    float sc = s[co];
    float v0 = w[co * CINC + ci]     * sc;
    float v1 = w[co * CINC + ci + 1] * sc;
    u32 lo, hi = packsplit(v0, v1, lo);
    *(u32*)&g_w1h[co * 128 + pair] = hi;
    *(u32*)&g_w1l[co * 128 + pair] = lo;
}

// ---------------- pre-split x into channel-pair-packed bf16x2 ----------------
__global__ void k_split_x(const float* __restrict__ x)
{
    int idx = blockIdx.x * 256 + threadIdx.x;        // BN*128*HW = 16,777,216
    int hw   = idx & (HWSZ - 1);
    int rest = idx >> 14;
    int cp   = rest & 127;
    int b    = rest >> 7;
    const float* p = x + ((size_t)(b * CINC + 2 * cp)) * HWSZ + hw;
    float v0 = p[0];
    float v1 = p[HWSZ];
    u32 lo, hi = packsplit(v0, v1, lo);
    g_xh[idx] = hi;
    g_xl[idx] = lo;
}

// ---------------- A tile via cp.async (16B chunks, source rows match tile rows) ----------------
__device__ __forceinline__ void build_A_async(u32 sb, u32 offA, int tid,
                                              const __nv_bfloat162* __restrict__ wh,
                                              const __nv_bfloat162* __restrict__ wl,
                                              int rsp /*pairs*/, int pair0)
{
#pragma unroll
    for (int q = 0; q < 2; q++) {
        int slot = tid + 512 * q;            // 1024 x 16B = 16KB per half
        int co = slot >> 3;
        int c  = slot & 7;
        u32 d = SWZ((u32)(co * 128 + c * 16));
        const char* sh = (const char*)(wh + (size_t)co * rsp + pair0) + c * 16;
        const char* sl = (const char*)(wl + (size_t)co * rsp + pair0) + c * 16;
        cpa16(sb + offA + d, sh);
        cpa16(sb + offA + 16384 + d, sl);
    }
}

// ---------------- B staged through registers (pre-split u32 words) ----------------
struct BReg { u32 h[8], l[8]; u32 th, tl; };

__device__ __forceinline__ void ldg_B(BReg& r, int tid,
                                      const u32* __restrict__ srch, const u32* __restrict__ srcl,
                                      int nchp /*channel pairs*/, int b, int cp0, int srow)
{
    const size_t HW = (size_t)HWSZ;
    bool rowok = (srow >= 0) && (srow < HH);
    size_t base = ((size_t)(b * nchp + cp0) * HH + (rowok ? srow : 0)) * WW;
    const u32* bh = srch + base;
    const u32* bl = srcl + base;
    int p  = tid & 127;
    int gp = tid >> 7;
    int spx = p - 1;
    bool okm = rowok && (spx >= 0);
#pragma unroll
    for (int q = 0; q < 8; q++) {
        int cpq = gp * 8 + q;
        r.h[q] = okm ? bh[(size_t)cpq * HW + spx] : 0u;
        r.l[q] = okm ? bl[(size_t)cpq * HW + spx] : 0u;
    }
    if (tid < 128) {
        int rr = 128 + (tid >> 5);
        int pc = tid & 31;                   // channel pair index
        int sp2 = rr - 1;
        bool ok = rowok && (sp2 < WW);
        r.th = ok ? bh[(size_t)pc * HW + sp2] : 0u;
        r.tl = ok ? bl[(size_t)pc * HW + sp2] : 0u;
    }
}

__device__ __forceinline__ void st_B(const BReg& r, u32 sb, u32 offB, int tid)
{
    int p  = tid & 127;
    int gp = tid >> 7;
#pragma unroll
    for (int q = 0; q < 8; q++) {
        int cil = gp * 16 + 2 * q;
        u32 sw = SWZ((u32)(p * 128 + 2 * cil));
        asm volatile("st.shared.b32 [%0], %1;" :: "r"(sb + offB + sw), "r"(r.h[q]) : "memory");
        asm volatile("st.shared.b32 [%0], %1;" :: "r"(sb + offB + BSZ + sw), "r"(r.l[q]) : "memory");
    }
    if (tid < 128) {
        int rr = 128 + (tid >> 5);
        int pc = tid & 31;
        u32 sw = SWZ((u32)(rr * 128 + 4 * pc));
        asm volatile("st.shared.b32 [%0], %1;" :: "r"(sb + offB + sw), "r"(r.th) : "memory");
        asm volatile("st.shared.b32 [%0], %1;" :: "r"(sb + offB + BSZ + sw), "r"(r.tl) : "memory");
    }
}

// ---------------- mma over one 64-k chunk; B rows shifted by kw ----------------
__device__ __forceinline__ void mma_chunk(u32 sb, u32 offA, u32 offB, int kw,
                                          int wm, int wn, int lid, float acc[2][4][4])
{
    const u32 lrow  = (u32)(lid & 15) * 128;
    const u32 lkh   = (u32)((lid >> 4) << 4);
    const u32 brow0 = (u32)kw * 128 + lrow;
#pragma unroll
    for (int ks = 0; ks < 4; ks++) {
        const u32 kb = (u32)(ks * 32) + lkh;
        u32 ah[2][4], al[2][4], bh[2][4], bl[2][4];
#pragma unroll
        for (int mt = 0; mt < 2; mt++) {
            u32 off = SWZ((u32)((wm * 32 + mt * 16) * 128) + lrow + kb);
            ldm_x4(ah[mt], sb + offA + off);
            ldm_x4(al[mt], sb + offA + 16384 + off);
        }
#pragma unroll
        for (int bt = 0; bt < 2; bt++) {
            u32 off = SWZ((u32)((wn * 32 + bt * 16) * 128) + brow0 + kb);
            ldm_x4(bh[bt], sb + offB + off);
            ldm_x4(bl[bt], sb + offB + BSZ + off);
        }
#pragma unroll
        for (int mt = 0; mt < 2; mt++)
#pragma unroll
            for (int bt = 0; bt < 2; bt++)
#pragma unroll
                for (int j = 0; j < 2; j++) {
                    u32 BH2[2] = { bh[bt][j], bh[bt][j + 2] };
                    u32 BL2[2] = { bl[bt][j], bl[bt][j + 2] };
                    float* d = acc[mt][bt * 2 + j];
                    mma16816(d, ah[mt], BH2);
                    mma16816(d, ah[mt], BL2);
                    mma16816(d, al[mt], BH2);
                }
    }
}

// ---------------- fused 4-branch 3x3 conv + BN + relu (HMMA, B reg-pipelined) ----------------
// grid = (H=128, B=8, br=4), 512 threads; block tile 128co x 128px
// chunks: 12 = kh(3) x c0(4); steps: 36 = chunks x kw(3)
__global__ __launch_bounds__(512, 1)
void k_conv_branch(const float* __restrict__ ob0, const float* __restrict__ ob1,
                   const float* __restrict__ ob2, const float* __restrict__ ob3)
{
    extern __shared__ char smem_raw[];
    u32 sb = smem_u32(smem_raw);
    const int h  = blockIdx.x;
    const int b  = blockIdx.y;
    const int br = blockIdx.z;
    const int tid = threadIdx.x;
    const int wid = tid >> 5, lid = tid & 31;
    const int wm = wid >> 2, wn = wid & 3;

    float acc[2][4][4];
#pragma unroll
    for (int i = 0; i < 2; i++)
#pragma unroll
        for (int j = 0; j < 4; j++)
#pragma unroll
            for (int k = 0; k < 4; k++) acc[i][j][k] = 0.f;

    BReg breg;
    ldg_B(breg, tid, g_xh, g_xl, 128, b, 0, h - 1);  // chunk 0: kh=0, cp0=0
    {
        size_t t0 = (size_t)(br * 9) * 16384;        // step 0: kh=0,kw=0
        build_A_async(sb, OFF_A0, tid, g_wAh + t0, g_wAl + t0, 128, 0);
        CPA_COMMIT();
    }

    for (int ch = 0; ch < 12; ch++) {
        u32 offB = (ch & 1) ? OFF_B1 : OFF_B0;
        st_B(breg, sb, offB, tid);
        __syncthreads();
        if (ch + 1 < 12) {
            int kh2 = (ch + 1) >> 2, cp02 = ((ch + 1) & 3) * 32;
            ldg_B(breg, tid, g_xh, g_xl, 128, b, cp02, h + kh2 - 1);   // drains under MMAs
        }
#pragma unroll
        for (int kw = 0; kw < 3; kw++) {
            int step = ch * 3 + kw;
            CPA_WAIT0();
            __syncthreads();
            if (step + 1 < 36) {
                int s2 = step + 1, ch2 = s2 / 3, kw2 = s2 - ch2 * 3;
                int kh2 = ch2 >> 2, c02 = (ch2 & 3) * 64;
                size_t tn = (size_t)(br * 9 + kh2 * 3 + kw2) * 16384;
                build_A_async(sb, (s2 & 1) ? OFF_A1 : OFF_A0, tid,
                              g_wAh + tn, g_wAl + tn, 128, c02 >> 1);
                CPA_COMMIT();
            }
            mma_chunk(sb, (step & 1) ? OFF_A1 : OFF_A0, offB, kw, wm, wn, lid, acc);
        }
    }

    const float* ob = (br == 0) ? ob0 : (br == 1) ? ob1 : (br == 2) ? ob2 : ob3;
    float* yb = g_y[br];
#pragma unroll
    for (int mt = 0; mt < 2; mt++) {
        int r0 = wm * 32 + mt * 16 + (lid >> 2);
#pragma unroll
        for (int half = 0; half < 2; half++) {
            int co = r0 + half * 8;
            float sh = ob[co];
            float* row = yb + ((size_t)(b * CMID + co) * HH + h) * WW;
#pragma unroll
            for (int nf = 0; nf < 4; nf++) {
                int px = wn * 32 + nf * 8 + 2 * (lid & 3);
                float2 v;
                v.x = fmaxf(acc[mt][nf][half * 2 + 0] + sh, 0.f);
                v.y = fmaxf(acc[mt][nf][half * 2 + 1] + sh, 0.f);
                *(float2*)(row + px) = v;
            }
        }
    }
}

// ---------------- scans along W (warp-per-row, float4 + shfl scan) ----------------
__global__ void k_scan_w()
{
    int bc   = blockIdx.x;
    int wq   = threadIdx.x >> 5;
    int lane = threadIdx.x & 31;
    const size_t plane = (size_t)bc * HH * WW;
    for (int hr = wq; hr < HH; hr += 16) {
        const float4* yl4 = (const float4*)(g_y[0] + plane + (size_t)hr * WW);
        const float4* yr4 = (const float4*)(g_y[1] + plane + (size_t)hr * WW);
        float4 a = yl4[lane];
        float4 r = yr4[lane];
        float p0 = r.x, p1 = fmaxf(p0, r.y), p2 = fmaxf(p1, r.z), p3 = fmaxf(p2, r.w);
        float m = p3;
#pragma unroll
        for (int o = 1; o < 32; o <<= 1) {
            float v = __shfl_up_sync(0xffffffffu, m, o);
            if (lane >= o) m = fmaxf(m, v);
        }
        float ex = __shfl_up_sync(0xffffffffu, m, 1);
        if (lane == 0) ex = -INFINITY;
        float q3 = a.w, q2 = fmaxf(q3, a.z), q1 = fmaxf(q2, a.y), q0 = fmaxf(q1, a.x);
        float mm = q0;
#pragma unroll
        for (int o = 1; o < 32; o <<= 1) {
            float v = __shfl_down_sync(0xffffffffu, mm, o);
            if (lane + o < 32) mm = fmaxf(mm, v);
        }
        float exr = __shfl_down_sync(0xffffffffu, mm, 1);
        if (lane == 31) exr = -INFINITY;
        float4 o4;
        o4.x = fmaxf(ex, p0) + fmaxf(exr, q0);
        o4.y = fmaxf(ex, p1) + fmaxf(exr, q1);
        o4.z = fmaxf(ex, p2) + fmaxf(exr, q2);
        o4.w = fmaxf(ex, p3) + fmaxf(exr, q3);
        ((float4*)(g_S + plane + (size_t)hr * WW))[lane] = o4;
    }
}

// ---------------- scans along H + emit split S (channel-pair packed) ----------------
// grid = BN*64 (channel pairs), 128 threads (w)
__global__ void k_scan_h()
{
    int bp = blockIdx.x;
    int b  = bp >> 6, cp = bp & 63;
    int w  = threadIdx.x;
    int c0 = 2 * cp;
    const size_t pl0 = ((size_t)(b * CMID + c0)) * HWSZ + w;
    const size_t pl1 = pl0 + HWSZ;
    const float* yt = g_y[2];
    const float* yv = g_y[3];
    float* S = g_S;
    float m0 = -INFINITY, m1 = -INFINITY;
    for (int hq = HH - 1; hq >= 0; --hq) {
        size_t o = (size_t)hq * WW;
        m0 = fmaxf(m0, yt[pl0 + o]); S[pl0 + o] += m0;
        m1 = fmaxf(m1, yt[pl1 + o]); S[pl1 + o] += m1;
    }
    m0 = -INFINITY; m1 = -INFINITY;
    u32* oh = g_Sh + ((size_t)(b * 64 + cp)) * HWSZ + w;
    u32* ol = g_Sl + ((size_t)(b * 64 + cp)) * HWSZ + w;
    for (int hq = 0; hq < HH; ++hq) {
        size_t o = (size_t)hq * WW;
        m0 = fmaxf(m0, yv[pl0 + o]);
        m1 = fmaxf(m1, yv[pl1 + o]);
        float f0 = S[pl0 + o] + m0;
        float f1 = S[pl1 + o] + m1;
        u32 lo, hi = packsplit(f0, f1, lo);
        oh[o] = hi;
        ol[o] = lo;
    }
}

// ---------------- conv2 3x3 over S + 1x1 skip over x + relu -> out ----------------
// grid = (H=128, B=8, ct=2), 512 threads
// phase1: 6 chunks (kh x 2 c0) x 3 kw = 18 steps; phase2: 4 chunks x 1 step = 4 steps
__device__ __forceinline__ void prefetch_A_out(u32 sb, int tid, int ct, int s)
{
    if (s < 18) {
        int ch = s / 3, kw = s - ch * 3;
        int kh = ch >> 1, c0 = (ch & 1) * 64;
        size_t tn = ((size_t)(kh * 3 + kw) * 256 + ct * 128) * 64;
        build_A_async(sb, (s & 1) ? OFF_A1 : OFF_A0, tid, g_w2h + tn, g_w2l + tn, 64, c0 >> 1);
    } else {
        int c = s - 18;
        size_t tn = (size_t)(ct * 128) * 128;
        build_A_async(sb, (s & 1) ? OFF_A1 : OFF_A0, tid, g_w1h + tn, g_w1l + tn, 128, c * 32);
    }
    CPA_COMMIT();
}

__global__ __launch_bounds__(512, 1)
void k_conv_out(const float* __restrict__ o2v, const float* __restrict__ o1v,
                float* __restrict__ out)
{
    extern __shared__ char smem_raw[];
    u32 sb = smem_u32(smem_raw);
    const int h  = blockIdx.x;
    const int b  = blockIdx.y;
    const int ct = blockIdx.z;
    const int tid = threadIdx.x;
    const int wid = tid >> 5, lid = tid & 31;
    const int wm = wid >> 2, wn = wid & 3;

    float acc[2][4][4];
#pragma unroll
    for (int i = 0; i < 2; i++)
#pragma unroll
        for (int j = 0; j < 4; j++)
#pragma unroll
            for (int k = 0; k < 4; k++) acc[i][j][k] = 0.f;

    BReg breg;
    ldg_B(breg, tid, g_Sh, g_Sl, 64, b, 0, h - 1);   // phase1 chunk 0
    prefetch_A_out(sb, tid, ct, 0);

    // phase 1: 3x3 conv over split S
    for (int ch = 0; ch < 6; ch++) {
        u32 offB = (ch & 1) ? OFF_B1 : OFF_B0;
        st_B(breg, sb, offB, tid);
        __syncthreads();
        if (ch + 1 < 6) {
            int kh2 = (ch + 1) >> 1, cp02 = ((ch + 1) & 1) * 32;
            ldg_B(breg, tid, g_Sh, g_Sl, 64, b, cp02, h + kh2 - 1);
        } else {
            ldg_B(breg, tid, g_xh, g_xl, 128, b, 0, h);   // bridge to phase 2
        }
#pragma unroll
        for (int kw = 0; kw < 3; kw++) {
            int step = ch * 3 + kw;
            CPA_WAIT0();
            __syncthreads();
            if (step + 1 < 22) prefetch_A_out(sb, tid, ct, step + 1);
            mma_chunk(sb, (step & 1) ? OFF_A1 : OFF_A0, offB, kw, wm, wn, lid, acc);
        }
    }
    // phase 2: 1x1 skip over x (brow offset = 1 reads unshifted pixels)
    for (int c = 0; c < 4; c++) {
        int ch = 6 + c;
        u32 offB = (ch & 1) ? OFF_B1 : OFF_B0;
        st_B(breg, sb, offB, tid);
        __syncthreads();
        if (c + 1 < 4) ldg_B(breg, tid, g_xh, g_xl, 128, b, (c + 1) * 32, h);
        int step = 18 + c;
        CPA_WAIT0();
        __syncthreads();
        if (step + 1 < 22) prefetch_A_out(sb, tid, ct, step + 1);
        mma_chunk(sb, (step & 1) ? OFF_A1 : OFF_A0, offB, 1, wm, wn, lid, acc);
    }

#pragma unroll
    for (int mt = 0; mt < 2; mt++) {
        int r0 = wm * 32 + mt * 16 + (lid >> 2);
#pragma unroll
        for (int half = 0; half < 2; half++) {
            int co = ct * 128 + r0 + half * 8;
            float sh = o2v[co] + o1v[co];
            float* row = out + ((size_t)(b * COUTC + co) * HH + h) * WW;
#pragma unroll
            for (int nf = 0; nf < 4; nf++) {
                int px = wn * 32 + nf * 8 + 2 * (lid & 3);
                float2 v;
                v.x = fmaxf(acc[mt][nf][half * 2 + 0] + sh, 0.f);
                v.y = fmaxf(acc[mt][nf][half * 2 + 1] + sh, 0.f);
                *(float2*)(row + px) = v;
            }
        }
    }
}

// ---------------- launch ----------------
extern "C" void kernel_launch(void* const* d_in, const int* in_sizes, int n_in,
                              void* d_out, int out_size)
{
    const float* x   = (const float*)d_in[0];
    const float* w_l = (const float*)d_in[1];
    const float* s_l = (const float*)d_in[2];
    const float* o_l = (const float*)d_in[3];
    const float* w_r = (const float*)d_in[4];
    const float* s_r = (const float*)d_in[5];
    const float* o_r = (const float*)d_in[6];
    const float* w_t = (const float*)d_in[7];
    const float* s_t = (const float*)d_in[8];
    const float* o_t = (const float*)d_in[9];
    const float* w_b = (const float*)d_in[10];
    const float* s_b = (const float*)d_in[11];
    const float* o_b = (const float*)d_in[12];
    const float* w2  = (const float*)d_in[13];
    const float* s2  = (const float*)d_in[14];
    const float* o2  = (const float*)d_in[15];
    const float* w1  = (const float*)d_in[16];
    const float* s1  = (const float*)d_in[17];
    const float* o1  = (const float*)d_in[18];
    float* out = (float*)d_out;

    cudaFuncSetAttribute(k_conv_branch, cudaFuncAttributeMaxDynamicSharedMemorySize, SMEM_BYTES);
    cudaFuncSetAttribute(k_conv_out,    cudaFuncAttributeMaxDynamicSharedMemorySize, SMEM_BYTES);

    k_repack_br<<<576, 256>>>(w_l, s_l, 0);
    k_repack_br<<<576, 256>>>(w_r, s_r, 1);
    k_repack_br<<<576, 256>>>(w_t, s_t, 2);
    k_repack_br<<<576, 256>>>(w_b, s_b, 3);
    k_repack_w2<<<576, 256>>>(w2, s2);
    k_repack_w1<<<128, 256>>>(w1, s1);
    k_split_x<<<65536, 256>>>(x);

    dim3 g1(HH, BN, 4);
    k_conv_branch<<<g1, 512, SMEM_BYTES>>>(o_l, o_r, o_t, o_b);
    k_scan_w<<<BN * CMID, 512>>>();
    k_scan_h<<<BN * 64, 128>>>();
    dim3 g3(HH, BN, 2);
    k_conv_out<<<g3, 512, SMEM_BYTES>>>(o2, o1, out);
}

// round 10
// speedup vs baseline: 1.0333x; 1.0333x over previous
#include <cuda_runtime.h>
#include <cuda_bf16.h>
#include <cstdint>
#include <math.h>

#define BN    8
#define CINC  256
#define CMID  128
#define COUTC 256
#define HH    128
#define WW    128
#define HWSZ  16384

typedef uint32_t u32;

// ---------------- scratch (static __device__ — allocation-free) ----------------
__device__ float g_y[4][BN * CMID * HH * WW];  // branch conv outputs (post-relu)
__device__ float g_S[BN * CMID * HH * WW];     // sum of 4 scanned branches
// bf16-split weights: branch [tap=br*9+kh*3+kw][co=128][cipair=128]
__device__ __align__(16) __nv_bfloat162 g_wAh[36 * 128 * 128];
__device__ __align__(16) __nv_bfloat162 g_wAl[36 * 128 * 128];
__device__ __align__(16) __nv_bfloat162 g_w2h[9 * 256 * 64];   // [t][co=256][cipair=64]
__device__ __align__(16) __nv_bfloat162 g_w2l[9 * 256 * 64];
__device__ __align__(16) __nv_bfloat162 g_w1h[256 * 128];      // [co=256][cipair=128]
__device__ __align__(16) __nv_bfloat162 g_w1l[256 * 128];

// ---------------- helpers ----------------
__device__ __forceinline__ u32 smem_u32(const void* p) {
    u32 a;
    asm("{ .reg .u64 t; cvta.to.shared.u64 t, %1; cvt.u32.u64 %0, t; }" : "=r"(a) : "l"(p));
    return a;
}

// XOR swizzle: byte bits [6:4] ^= bits [9:7]  (rows are 128B)
#define SWZ(off) ((off) ^ (((off) >> 3) & 0x70))

__device__ __forceinline__ void ldm_x4(u32* r, u32 addr) {
    asm volatile("ldmatrix.sync.aligned.m8n8.x4.shared.b16 {%0,%1,%2,%3}, [%4];"
                 : "=r"(r[0]), "=r"(r[1]), "=r"(r[2]), "=r"(r[3]) : "r"(addr));
}
__device__ __forceinline__ void mma16816(float* d, const u32* a, const u32* b) {
    asm volatile("mma.sync.aligned.m16n8k16.row.col.f32.bf16.bf16.f32 "
                 "{%0,%1,%2,%3}, {%4,%5,%6,%7}, {%8,%9}, {%0,%1,%2,%3};"
                 : "+f"(d[0]), "+f"(d[1]), "+f"(d[2]), "+f"(d[3])
                 : "r"(a[0]), "r"(a[1]), "r"(a[2]), "r"(a[3]), "r"(b[0]), "r"(b[1]));
}
__device__ __forceinline__ void cpa16(u32 d, const void* s) {
    asm volatile("cp.async.cg.shared.global [%0], [%1], 16;" :: "r"(d), "l"(s));
}
#define CPA_COMMIT() asm volatile("cp.async.commit_group;" ::: "memory")
#define CPA_WAIT0()  asm volatile("cp.async.wait_group 0;" ::: "memory")

// smem: two A buffers (256 rows: hi 32KB + lo 32KB), two B buffers (132 rows, hi+lo)
#define BSZ    16896                    // 132 * 128 bytes
#define ASZ    32768                    // 256 * 128 bytes (one half)
#define OFF_A0 0
#define OFF_A1 65536
#define OFF_B0 131072
#define OFF_B1 (131072 + 2 * BSZ)       // 164864
#define SMEM_BYTES (OFF_B1 + 2 * BSZ)   // 198656

__device__ __forceinline__ void split2(float v0, float v1, u32 sb, u32 offB, u32 off) {
    __nv_bfloat16 h0 = __float2bfloat16(v0), h1 = __float2bfloat16(v1);
    __nv_bfloat16 l0 = __float2bfloat16(v0 - __bfloat162float(h0));
    __nv_bfloat16 l1 = __float2bfloat16(v1 - __bfloat162float(h1));
    u32 sw = SWZ(off);
    u32 hv, lv;
    asm("mov.b32 %0, {%1, %2};" : "=r"(hv) : "h"(*(unsigned short*)&h0), "h"(*(unsigned short*)&h1));
    asm("mov.b32 %0, {%1, %2};" : "=r"(lv) : "h"(*(unsigned short*)&l0), "h"(*(unsigned short*)&l1));
    asm volatile("st.shared.b32 [%0], %1;" :: "r"(sb + offB + sw), "r"(hv) : "memory");
    asm volatile("st.shared.b32 [%0], %1;" :: "r"(sb + offB + BSZ + sw), "r"(lv) : "memory");
}

// ---------------- weight repack (+BN scale fold, bf16 hi/lo split) ----------------
__global__ void k_repack_br(const float* __restrict__ w, const float* __restrict__ s, int br)
{
    int slot = blockIdx.x * 256 + threadIdx.x;       // 9*128*128
    if (slot >= 147456) return;
    int pair = slot & 127;
    int co   = (slot >> 7) & 127;
    int t    = slot >> 14;
    int kh = t / 3, kw = t % 3;
    int ci = pair * 2;
    float sc = s[co];
    float v0 = w[((co * CINC + ci)     * 3 + kh) * 3 + kw] * sc;
    float v1 = w[((co * CINC + ci + 1) * 3 + kh) * 3 + kw] * sc;
    __nv_bfloat16 h0 = __float2bfloat16(v0), h1 = __float2bfloat16(v1);
    __nv_bfloat16 l0 = __float2bfloat16(v0 - __bfloat162float(h0));
    __nv_bfloat16 l1 = __float2bfloat16(v1 - __bfloat162float(h1));
    int idx = ((br * 9 + t) * 128 + co) * 128 + pair;
    g_wAh[idx] = __halves2bfloat162(h0, h1);
    g_wAl[idx] = __halves2bfloat162(l0, l1);
}

__global__ void k_repack_w2(const float* __restrict__ w, const float* __restrict__ s)
{
    int slot = blockIdx.x * 256 + threadIdx.x;       // 9*256*64
    if (slot >= 147456) return;
    int pair = slot & 63;
    int co   = (slot >> 6) & 255;
    int t    = slot >> 14;
    int kh = t / 3, kw = t % 3;
    int ci = pair * 2;
    float sc = s[co];
    float v0 = w[((co * CMID + ci)     * 3 + kh) * 3 + kw] * sc;
    float v1 = w[((co * CMID + ci + 1) * 3 + kh) * 3 + kw] * sc;
    __nv_bfloat16 h0 = __float2bfloat16(v0), h1 = __float2bfloat16(v1);
    __nv_bfloat16 l0 = __float2bfloat16(v0 - __bfloat162float(h0));
    __nv_bfloat16 l1 = __float2bfloat16(v1 - __bfloat162float(h1));
    int idx = (t * 256 + co) * 64 + pair;
    g_w2h[idx] = __halves2bfloat162(h0, h1);
    g_w2l[idx] = __halves2bfloat162(l0, l1);
}

__global__ void k_repack_w1(const float* __restrict__ w, const float* __restrict__ s)
{
    int slot = blockIdx.x * 256 + threadIdx.x;       // 256*128
    if (slot >= 32768) return;
    int pair = slot & 127;
    int co   = slot >> 7;
    int ci = pair * 2;
    float sc = s[co];
    float v0 = w[co * CINC + ci]     * sc;
    float v1 = w[co * CINC + ci + 1] * sc;
    __nv_bfloat16 h0 = __float2bfloat16(v0), h1 = __float2bfloat16(v1);
    __nv_bfloat16 l0 = __float2bfloat16(v0 - __bfloat162float(h0));
    __nv_bfloat16 l1 = __float2bfloat16(v1 - __bfloat162float(h1));
    g_w1h[co * 128 + pair] = __halves2bfloat162(h0, h1);
    g_w1l[co * 128 + pair] = __halves2bfloat162(l0, l1);
}

// ---------------- A tile via cp.async: 256 co rows x 64 bf16 cols ----------------
// rows >=128 read from (wh + hi_off) region; rsp = source row stride in pairs
__device__ __forceinline__ void build_A_async(u32 sb, u32 offA, int tid,
                                              const __nv_bfloat162* __restrict__ wh,
                                              const __nv_bfloat162* __restrict__ wl,
                                              int rsp, int pair0, size_t hi_off)
{
#pragma unroll
    for (int q = 0; q < 4; q++) {
        int slot = tid + 512 * q;            // 2048 x 16B = 32KB per half
        int co = slot >> 3;
        int c  = slot & 7;
        u32 d = SWZ((u32)(co * 128 + c * 16));
        size_t idx = (co < 128 ? (size_t)co * rsp : hi_off + (size_t)(co - 128) * rsp) + pair0;
        const char* sh = (const char*)(wh + idx) + c * 16;
        const char* sl = (const char*)(wl + idx) + c * 16;
        cpa16(sb + offA + d, sh);
        cpa16(sb + offA + ASZ + d, sl);
    }
}

// ---------------- B staged through registers ----------------
struct BReg { float m[16]; float t0, t1; };

__device__ __forceinline__ void ldg_B(BReg& r, int tid, const float* __restrict__ src,
                                      int nchan, int b, int c0, int srow)
{
    const size_t HW = (size_t)HWSZ;
    bool rowok = (srow >= 0) && (srow < HH);
    const float* base = src + ((size_t)(b * nchan + c0) * HH + (rowok ? srow : 0)) * WW;
    int p  = tid & 127;
    int gp = tid >> 7;
    int spx = p - 1;
    bool okm = rowok && (spx >= 0);
    const float* bp = base + spx;
#pragma unroll
    for (int q = 0; q < 8; q++) {
        int cil = gp * 16 + 2 * q;
        r.m[2 * q]     = okm ? bp[(size_t)cil * HW] : 0.f;
        r.m[2 * q + 1] = okm ? bp[(size_t)(cil + 1) * HW] : 0.f;
    }
    if (tid < 128) {
        int rr = 128 + (tid >> 5);
        int pc = tid & 31;
        int cil = 2 * pc;
        int sp2 = rr - 1;
        bool ok = rowok && (sp2 < WW);
        r.t0 = ok ? base[(size_t)cil * HW + sp2] : 0.f;
        r.t1 = ok ? base[(size_t)(cil + 1) * HW + sp2] : 0.f;
    }
}

__device__ __forceinline__ void st_B(const BReg& r, u32 sb, u32 offB, int tid)
{
    int p  = tid & 127;
    int gp = tid >> 7;
#pragma unroll
    for (int q = 0; q < 8; q++) {
        int cil = gp * 16 + 2 * q;
        split2(r.m[2 * q], r.m[2 * q + 1], sb, offB, (u32)(p * 128 + 2 * cil));
    }
    if (tid < 128) {
        int rr = 128 + (tid >> 5);
        int pc = tid & 31;
        split2(r.t0, r.t1, sb, offB, (u32)(rr * 128 + 4 * pc));
    }
}

// ---------------- mma over one 64-k chunk; M=256, warp = 32co x 64px ----------------
// 16 warps: wm = wid>>1 (0..7), wn = wid&1 (0..1)
__device__ __forceinline__ void mma_chunk(u32 sb, u32 offA, u32 offB, int kw,
                                          int wm, int wn, int lid, float acc[2][8][4])
{
    const u32 lrow  = (u32)(lid & 15) * 128;
    const u32 lkh   = (u32)((lid >> 4) << 4);
    const u32 brow0 = (u32)kw * 128 + lrow;
#pragma unroll
    for (int ks = 0; ks < 4; ks++) {
        const u32 kb = (u32)(ks * 32) + lkh;
        u32 ah[2][4], al[2][4], bh[4][4], bl[4][4];
#pragma unroll
        for (int mt = 0; mt < 2; mt++) {
            u32 off = SWZ((u32)((wm * 32 + mt * 16) * 128) + lrow + kb);
            ldm_x4(ah[mt], sb + offA + off);
            ldm_x4(al[mt], sb + offA + ASZ + off);
        }
#pragma unroll
        for (int bt = 0; bt < 4; bt++) {
            u32 off = SWZ((u32)((wn * 64 + bt * 16) * 128) + brow0 + kb);
            ldm_x4(bh[bt], sb + offB + off);
            ldm_x4(bl[bt], sb + offB + BSZ + off);
        }
#pragma unroll
        for (int mt = 0; mt < 2; mt++)
#pragma unroll
            for (int bt = 0; bt < 4; bt++)
#pragma unroll
                for (int j = 0; j < 2; j++) {
                    u32 BH2[2] = { bh[bt][j], bh[bt][j + 2] };
                    u32 BL2[2] = { bl[bt][j], bl[bt][j + 2] };
                    float* d = acc[mt][bt * 2 + j];
                    mma16816(d, ah[mt], BH2);
                    mma16816(d, ah[mt], BL2);
                    mma16816(d, al[mt], BH2);
                }
    }
}

// ---------------- fused branch-PAIR 3x3 conv + BN + relu ----------------
// grid = (H=128, B=8, pair=2): pair 0 -> branches {0,1}, pair 1 -> {2,3}
// block tile 256co(two branches) x 128px; same B tile serves both.
__global__ __launch_bounds__(512, 1)
void k_conv_branch(const float* __restrict__ x,
                   const float* __restrict__ ob0, const float* __restrict__ ob1,
                   const float* __restrict__ ob2, const float* __restrict__ ob3)
{
    extern __shared__ char smem_raw[];
    u32 sb = smem_u32(smem_raw);
    const int h  = blockIdx.x;
    const int b  = blockIdx.y;
    const int bz = blockIdx.z;
    const int tid = threadIdx.x;
    const int wid = tid >> 5, lid = tid & 31;
    const int wm = wid >> 1, wn = wid & 1;
    const size_t HIOFF = 9 * 16384;                  // +1 branch in g_wA

    float acc[2][8][4];
#pragma unroll
    for (int i = 0; i < 2; i++)
#pragma unroll
        for (int j = 0; j < 8; j++)
#pragma unroll
            for (int k = 0; k < 4; k++) acc[i][j][k] = 0.f;

    BReg breg;
    ldg_B(breg, tid, x, CINC, b, 0, h - 1);          // chunk 0: kh=0, c0=0
    {
        size_t t0 = (size_t)(bz * 2 * 9) * 16384;    // step 0: kh=0,kw=0, branch 2*bz
        build_A_async(sb, OFF_A0, tid, g_wAh + t0, g_wAl + t0, 128, 0, HIOFF);
        CPA_COMMIT();
    }

    for (int ch = 0; ch < 12; ch++) {
        u32 offB = (ch & 1) ? OFF_B1 : OFF_B0;
        st_B(breg, sb, offB, tid);
        __syncthreads();
        if (ch + 1 < 12) {
            int kh2 = (ch + 1) >> 2, c02 = ((ch + 1) & 3) * 64;
            ldg_B(breg, tid, x, CINC, b, c02, h + kh2 - 1);    // drains under MMAs
        }
#pragma unroll
        for (int kw = 0; kw < 3; kw++) {
            int step = ch * 3 + kw;
            CPA_WAIT0();
            __syncthreads();
            if (step + 1 < 36) {
                int s2 = step + 1, ch2 = s2 / 3, kw2 = s2 - ch2 * 3;
                int kh2 = ch2 >> 2, c02 = (ch2 & 3) * 64;
                size_t tn = (size_t)(bz * 2 * 9 + kh2 * 3 + kw2) * 16384;
                build_A_async(sb, (s2 & 1) ? OFF_A1 : OFF_A0, tid,
                              g_wAh + tn, g_wAl + tn, 128, c02 >> 1, HIOFF);
                CPA_COMMIT();
            }
            mma_chunk(sb, (step & 1) ? OFF_A1 : OFF_A0, offB, kw, wm, wn, lid, acc);
        }
    }

    const float* obs[4] = { ob0, ob1, ob2, ob3 };
#pragma unroll
    for (int mt = 0; mt < 2; mt++) {
        int r0 = wm * 32 + mt * 16 + (lid >> 2);     // 0..255
#pragma unroll
        for (int half = 0; half < 2; half++) {
            int co  = r0 + half * 8;
            int brl = co >> 7;                       // 0/1 within pair (constant per warp)
            int cob = co & 127;
            float sh = obs[2 * bz + brl][cob];
            float* row = g_y[2 * bz + brl] + ((size_t)(b * CMID + cob) * HH + h) * WW;
#pragma unroll
            for (int nf = 0; nf < 8; nf++) {
                int px = wn * 64 + nf * 8 + 2 * (lid & 3);
                float2 v;
                v.x = fmaxf(acc[mt][nf][half * 2 + 0] + sh, 0.f);
                v.y = fmaxf(acc[mt][nf][half * 2 + 1] + sh, 0.f);
                *(float2*)(row + px) = v;
            }
        }
    }
}

// ---------------- scans along W (warp-per-row, float4 + shfl scan) ----------------
__global__ void k_scan_w()
{
    int bc   = blockIdx.x;
    int wq   = threadIdx.x >> 5;
    int lane = threadIdx.x & 31;
    const size_t plane = (size_t)bc * HH * WW;
    for (int hr = wq; hr < HH; hr += 16) {
        const float4* yl4 = (const float4*)(g_y[0] + plane + (size_t)hr * WW);
        const float4* yr4 = (const float4*)(g_y[1] + plane + (size_t)hr * WW);
        float4 a = yl4[lane];
        float4 r = yr4[lane];
        float p0 = r.x, p1 = fmaxf(p0, r.y), p2 = fmaxf(p1, r.z), p3 = fmaxf(p2, r.w);
        float m = p3;
#pragma unroll
        for (int o = 1; o < 32; o <<= 1) {
            float v = __shfl_up_sync(0xffffffffu, m, o);
            if (lane >= o) m = fmaxf(m, v);
        }
        float ex = __shfl_up_sync(0xffffffffu, m, 1);
        if (lane == 0) ex = -INFINITY;
        float q3 = a.w, q2 = fmaxf(q3, a.z), q1 = fmaxf(q2, a.y), q0 = fmaxf(q1, a.x);
        float mm = q0;
#pragma unroll
        for (int o = 1; o < 32; o <<= 1) {
            float v = __shfl_down_sync(0xffffffffu, mm, o);
            if (lane + o < 32) mm = fmaxf(mm, v);
        }
        float exr = __shfl_down_sync(0xffffffffu, mm, 1);
        if (lane == 31) exr = -INFINITY;
        float4 o4;
        o4.x = fmaxf(ex, p0) + fmaxf(exr, q0);
        o4.y = fmaxf(ex, p1) + fmaxf(exr, q1);
        o4.z = fmaxf(ex, p2) + fmaxf(exr, q2);
        o4.w = fmaxf(ex, p3) + fmaxf(exr, q3);
        ((float4*)(g_S + plane + (size_t)hr * WW))[lane] = o4;
    }
}

// ---------------- scans along H (coalesced columns) ----------------
__global__ void k_scan_h()
{
    int bc = blockIdx.x;
    int w  = threadIdx.x;
    const float* yt = g_y[2] + (size_t)bc * (HH * WW) + w;
    const float* yv = g_y[3] + (size_t)bc * (HH * WW) + w;
    float* Sp = g_S + (size_t)bc * (HH * WW) + w;
    float m = -INFINITY;
    for (int hq = HH - 1; hq >= 0; --hq) { m = fmaxf(m, yt[hq * WW]); Sp[hq * WW] += m; }
    m = -INFINITY;
    for (int hq = 0; hq < HH; ++hq)      { m = fmaxf(m, yv[hq * WW]); Sp[hq * WW] += m; }
}

// ---------------- conv2 3x3 over S + 1x1 skip over x + relu -> out ----------------
// grid = (H=128, B=8, 1), 512 threads, M=256 (all co)
// phase1: 6 chunks (kh x 2 c0) x 3 kw = 18 steps; phase2: 4 chunks x 1 step
__device__ __forceinline__ void prefetch_A_out(u32 sb, int tid, int s)
{
    if (s < 18) {
        int ch = s / 3, kw = s - ch * 3;
        int kh = ch >> 1, c0 = (ch & 1) * 64;
        size_t tn = (size_t)(kh * 3 + kw) * 256 * 64;
        build_A_async(sb, (s & 1) ? OFF_A1 : OFF_A0, tid,
                      g_w2h + tn, g_w2l + tn, 64, c0 >> 1, (size_t)128 * 64);
    } else {
        int c = s - 18;
        build_A_async(sb, (s & 1) ? OFF_A1 : OFF_A0, tid,
                      g_w1h, g_w1l, 128, c * 32, (size_t)128 * 128);
    }
    CPA_COMMIT();
}

__global__ __launch_bounds__(512, 1)
void k_conv_out(const float* __restrict__ x,
                const float* __restrict__ o2v, const float* __restrict__ o1v,
                float* __restrict__ out)
{
    extern __shared__ char smem_raw[];
    u32 sb = smem_u32(smem_raw);
    const int h  = blockIdx.x;
    const int b  = blockIdx.y;
    const int tid = threadIdx.x;
    const int wid = tid >> 5, lid = tid & 31;
    const int wm = wid >> 1, wn = wid & 1;

    float acc[2][8][4];
#pragma unroll
    for (int i = 0; i < 2; i++)
#pragma unroll
        for (int j = 0; j < 8; j++)
#pragma unroll
            for (int k = 0; k < 4; k++) acc[i][j][k] = 0.f;

    BReg breg;
    ldg_B(breg, tid, g_S, CMID, b, 0, h - 1);        // phase1 chunk 0
    prefetch_A_out(sb, tid, 0);

    // phase 1: 3x3 conv over g_S
    for (int ch = 0; ch < 6; ch++) {
        u32 offB = (ch & 1) ? OFF_B1 : OFF_B0;
        st_B(breg, sb, offB, tid);
        __syncthreads();
        if (ch + 1 < 6) {
            int kh2 = (ch + 1) >> 1, c02 = ((ch + 1) & 1) * 64;
            ldg_B(breg, tid, g_S, CMID, b, c02, h + kh2 - 1);
        } else {
            ldg_B(breg, tid, x, CINC, b, 0, h);      // bridge to phase 2
        }
#pragma unroll
        for (int kw = 0; kw < 3; kw++) {
            int step = ch * 3 + kw;
            CPA_WAIT0();
            __syncthreads();
            if (step + 1 < 22) prefetch_A_out(sb, tid, step + 1);
            mma_chunk(sb, (step & 1) ? OFF_A1 : OFF_A0, offB, kw, wm, wn, lid, acc);
        }
    }
    // phase 2: 1x1 skip over x (brow offset = 1 reads unshifted pixels)
    for (int c = 0; c < 4; c++) {
        int ch = 6 + c;
        u32 offB = (ch & 1) ? OFF_B1 : OFF_B0;
        st_B(breg, sb, offB, tid);
        __syncthreads();
        if (c + 1 < 4) ldg_B(breg, tid, x, CINC, b, (c + 1) * 64, h);
        int step = 18 + c;
        CPA_WAIT0();
        __syncthreads();
        if (step + 1 < 22) prefetch_A_out(sb, tid, step + 1);
        mma_chunk(sb, (step & 1) ? OFF_A1 : OFF_A0, offB, 1, wm, wn, lid, acc);
    }

#pragma unroll
    for (int mt = 0; mt < 2; mt++) {
        int r0 = wm * 32 + mt * 16 + (lid >> 2);
#pragma unroll
        for (int half = 0; half < 2; half++) {
            int co = r0 + half * 8;                  // 0..255
            float sh = o2v[co] + o1v[co];
            float* row = out + ((size_t)(b * COUTC + co) * HH + h) * WW;
#pragma unroll
            for (int nf = 0; nf < 8; nf++) {
                int px = wn * 64 + nf * 8 + 2 * (lid & 3);
                float2 v;
                v.x = fmaxf(acc[mt][nf][half * 2 + 0] + sh, 0.f);
                v.y = fmaxf(acc[mt][nf][half * 2 + 1] + sh, 0.f);
                *(float2*)(row + px) = v;
            }
        }
    }
}

// ---------------- launch ----------------
extern "C" void kernel_launch(void* const* d_in, const int* in_sizes, int n_in,
                              void* d_out, int out_size)
{
    const float* x   = (const float*)d_in[0];
    const float* w_l = (const float*)d_in[1];
    const float* s_l = (const float*)d_in[2];
    const float* o_l = (const float*)d_in[3];
    const float* w_r = (const float*)d_in[4];
    const float* s_r = (const float*)d_in[5];
    const float* o_r = (const float*)d_in[6];
    const float* w_t = (const float*)d_in[7];
    const float* s_t = (const float*)d_in[8];
    const float* o_t = (const float*)d_in[9];
    const float* w_b = (const float*)d_in[10];
    const float* s_b = (const float*)d_in[11];
    const float* o_b = (const float*)d_in[12];
    const float* w2  = (const float*)d_in[13];
    const float* s2  = (const float*)d_in[14];
    const float* o2  = (const float*)d_in[15];
    const float* w1  = (const float*)d_in[16];
    const float* s1  = (const float*)d_in[17];
    const float* o1  = (const float*)d_in[18];
    float* out = (float*)d_out;

    cudaFuncSetAttribute(k_conv_branch, cudaFuncAttributeMaxDynamicSharedMemorySize, SMEM_BYTES);
    cudaFuncSetAttribute(k_conv_out,    cudaFuncAttributeMaxDynamicSharedMemorySize, SMEM_BYTES);

    k_repack_br<<<576, 256>>>(w_l, s_l, 0);
    k_repack_br<<<576, 256>>>(w_r, s_r, 1);
    k_repack_br<<<576, 256>>>(w_t, s_t, 2);
    k_repack_br<<<576, 256>>>(w_b, s_b, 3);
    k_repack_w2<<<576, 256>>>(w2, s2);
    k_repack_w1<<<128, 256>>>(w1, s1);

    dim3 g1(HH, BN, 2);
    k_conv_branch<<<g1, 512, SMEM_BYTES>>>(x, o_l, o_r, o_t, o_b);
    k_scan_w<<<BN * CMID, 512>>>();
    k_scan_h<<<BN * CMID, 128>>>();
    dim3 g3(HH, BN, 1);
    k_conv_out<<<g3, 512, SMEM_BYTES>>>(x, o2, o1, out);
}